// round 7
// baseline (speedup 1.0000x reference)
#include <cuda_runtime.h>
#include <math.h>

// ---------------- problem constants ----------------
#define BATCH   16
#define CIN     256
#define IMGH    64
#define IMGW    64
#define NPIX    4096          // 64*64
#define HEADS   4
#define DK      16
#define DV      64
#define RKS     7
#define TAPS    49            // 7*7
#define PADR    3

// ---------------- device scratch (globals: allowed) ----------------
__device__ float g_q[BATCH * 64 * NPIX];   // raw q projections [b][ch=h*16+k][p]
__device__ float g_k[BATCH * 16 * NPIX];   // raw k projections [b][k][p]
__device__ float g_v[BATCH * 64 * NPIX];   // raw v projections [b][v][p]
__device__ float g_sq[64], g_bq[64];       // BN fold for q: y = x*s + b
__device__ float g_sv[64], g_bv[64];       // BN fold for v
__device__ float g_lamc[BATCH * 16 * 64];  // lambda_c [b][k][v]

// ======================================================================
// K1: fused projection GEMM, double-buffered. Per batch:
// Y[144,4096] = W[144,256] * X[256,4096]; rows 0..63 q, 64..79 k, 80..143 v.
// 256 threads as 16(ty: row-group) x 16(tx: 8 contiguous pixels each).
// One __syncthreads per k-chunk; global loads of chunk i+1 overlap compute i.
// ======================================================================
__global__ __launch_bounds__(256)
void k_proj(const float* __restrict__ x,
            const float* __restrict__ Wq,
            const float* __restrict__ Wk,
            const float* __restrict__ Wv) {
    __shared__ float Xs[2][16][128];
    __shared__ float Ws[2][144][17];

    const int b   = blockIdx.y;
    const int p0  = blockIdx.x * 128;
    const int tid = threadIdx.x;
    const int ty  = tid >> 4;    // 0..15 row group
    const int tx  = tid & 15;    // 0..15 -> pixels tx*8..tx*8+7

    const float* xb = x + (size_t)b * CIN * NPIX;

    float acc[9][8];
#pragma unroll
    for (int i = 0; i < 9; ++i)
#pragma unroll
        for (int j = 0; j < 8; ++j) acc[i][j] = 0.f;

    float xr[8], wr[9];

    // ---- preload chunk 0 ----
#pragma unroll
    for (int r = 0; r < 8; ++r) {
        int idx = tid + r * 256;
        xr[r] = xb[(size_t)(idx >> 7) * NPIX + p0 + (idx & 127)];
    }
#pragma unroll
    for (int r = 0; r < 9; ++r) {
        int idx = tid + r * 256;
        int o = idx >> 4, cc = idx & 15;
        float w;
        if (o < 64)       w = Wq[o * CIN + cc];
        else if (o < 80)  w = Wk[(o - 64) * CIN + cc];
        else              w = Wv[(o - 80) * CIN + cc];
        wr[r] = w;
    }
#pragma unroll
    for (int r = 0; r < 8; ++r) {
        int idx = tid + r * 256;
        Xs[0][idx >> 7][idx & 127] = xr[r];
    }
#pragma unroll
    for (int r = 0; r < 9; ++r) {
        int idx = tid + r * 256;
        Ws[0][idx >> 4][idx & 15] = wr[r];
    }
    __syncthreads();

    for (int kchunk = 0; kchunk < 16; ++kchunk) {
        const int buf = kchunk & 1;
        const int c0n = (kchunk + 1) * 16;

        if (kchunk < 15) {   // issue global loads for next chunk (overlap compute)
#pragma unroll
            for (int r = 0; r < 8; ++r) {
                int idx = tid + r * 256;
                xr[r] = xb[(size_t)(c0n + (idx >> 7)) * NPIX + p0 + (idx & 127)];
            }
#pragma unroll
            for (int r = 0; r < 9; ++r) {
                int idx = tid + r * 256;
                int o = idx >> 4, cc = idx & 15;
                float w;
                if (o < 64)       w = Wq[o * CIN + c0n + cc];
                else if (o < 80)  w = Wk[(o - 64) * CIN + c0n + cc];
                else              w = Wv[(o - 80) * CIN + c0n + cc];
                wr[r] = w;
            }
        }

        // ---- compute on current buffer ----
#pragma unroll
        for (int cc = 0; cc < 16; ++cc) {
            float a[9];
#pragma unroll
            for (int i = 0; i < 9; ++i) a[i] = Ws[buf][ty + 16 * i][cc];
            float4 b0 = *(const float4*)&Xs[buf][cc][tx * 8];
            float4 b1 = *(const float4*)&Xs[buf][cc][tx * 8 + 4];
            float bb[8] = {b0.x, b0.y, b0.z, b0.w, b1.x, b1.y, b1.z, b1.w};
#pragma unroll
            for (int i = 0; i < 9; ++i)
#pragma unroll
                for (int j = 0; j < 8; ++j) acc[i][j] += a[i] * bb[j];
        }

        if (kchunk < 15) {   // store next chunk into the other buffer
#pragma unroll
            for (int r = 0; r < 8; ++r) {
                int idx = tid + r * 256;
                Xs[buf ^ 1][idx >> 7][idx & 127] = xr[r];
            }
#pragma unroll
            for (int r = 0; r < 9; ++r) {
                int idx = tid + r * 256;
                Ws[buf ^ 1][idx >> 4][idx & 15] = wr[r];
            }
        }
        __syncthreads();
    }

    // ---- store: thread owns 8 contiguous pixels -> 2x STG.128 per row ----
#pragma unroll
    for (int i = 0; i < 9; ++i) {
        int o = ty + 16 * i;
        float* dst;
        if (o < 64)      dst = g_q + ((size_t)b * 64 + o) * NPIX;
        else if (o < 80) dst = g_k + ((size_t)b * 16 + (o - 64)) * NPIX;
        else             dst = g_v + ((size_t)b * 64 + (o - 80)) * NPIX;
        float4 s0 = make_float4(acc[i][0], acc[i][1], acc[i][2], acc[i][3]);
        float4 s1 = make_float4(acc[i][4], acc[i][5], acc[i][6], acc[i][7]);
        *(float4*)(dst + p0 + tx * 8)     = s0;
        *(float4*)(dst + p0 + tx * 8 + 4) = s1;
    }
}

// ======================================================================
// K2: BN statistics -> folded scale/bias. 128 blocks, float4 loads.
// ======================================================================
__global__ __launch_bounds__(256)
void k_bnstats(const float* __restrict__ gamma_q, const float* __restrict__ beta_q,
               const float* __restrict__ gamma_v, const float* __restrict__ beta_v) {
    const int ch  = blockIdx.x;
    const int tid = threadIdx.x;

    const float* src;
    float gamma, beta;
    float *sdst, *bdst;
    if (ch < 64) {
        src = g_q + (size_t)ch * NPIX;
        gamma = gamma_q[ch]; beta = beta_q[ch];
        sdst = &g_sq[ch]; bdst = &g_bq[ch];
    } else {
        int c = ch - 64;
        src = g_v + (size_t)c * NPIX;
        gamma = gamma_v[c]; beta = beta_v[c];
        sdst = &g_sv[c]; bdst = &g_bv[c];
    }

    float s = 0.f, s2 = 0.f;
    for (int b = 0; b < BATCH; ++b) {
        const float* p = src + (size_t)b * 64 * NPIX;
        for (int i = tid * 4; i < NPIX; i += 1024) {
            float4 v = *(const float4*)(p + i);
            s  += v.x + v.y + v.z + v.w;
            s2 += v.x * v.x + v.y * v.y + v.z * v.z + v.w * v.w;
        }
    }
    __shared__ float ss[256], ss2[256];
    ss[tid] = s; ss2[tid] = s2;
    __syncthreads();
    for (int st = 128; st > 0; st >>= 1) {
        if (tid < st) { ss[tid] += ss[tid + st]; ss2[tid] += ss2[tid + st]; }
        __syncthreads();
    }
    if (tid == 0) {
        const float inv_n = 1.0f / 65536.0f;
        float mean = ss[0] * inv_n;
        float var  = ss2[0] * inv_n - mean * mean;
        float sc   = gamma * rsqrtf(var + 1e-5f);
        *sdst = sc;
        *bdst = beta - mean * sc;
    }
}

// ======================================================================
// K3: softmax over k row + lambda_c, fused, float4 over pixels.
// One block per (b, k) = 256 blocks.
// ======================================================================
__global__ __launch_bounds__(256)
void k_lamc() {
    const int bk  = blockIdx.x;
    const int b   = bk >> 4;
    const int kc  = bk & 15;
    const int tid = threadIdx.x;
    const int lane = tid & 31, wrp = tid >> 5;

    const float* krow = g_k + ((size_t)b * 16 + kc) * NPIX;
    const float* vb   = g_v + (size_t)b * 64 * NPIX;

    __shared__ float red[256];

    // pass 1: row max (float4)
    float m = -1e30f;
    for (int i = tid * 4; i < NPIX; i += 1024) {
        float4 kv = *(const float4*)(krow + i);
        m = fmaxf(m, fmaxf(fmaxf(kv.x, kv.y), fmaxf(kv.z, kv.w)));
    }
    red[tid] = m;
    __syncthreads();
    for (int st = 128; st > 0; st >>= 1) {
        if (tid < st) red[tid] = fmaxf(red[tid], red[tid + st]);
        __syncthreads();
    }
    m = red[0];
    __syncthreads();

    // pass 2: weighted sums (float4 pixels)
    float acc[64];
#pragma unroll
    for (int v = 0; v < 64; ++v) acc[v] = 0.f;
    float z = 0.f;

    for (int i = tid * 4; i < NPIX; i += 1024) {
        float4 kv = *(const float4*)(krow + i);
        float e0 = expf(kv.x - m);
        float e1 = expf(kv.y - m);
        float e2 = expf(kv.z - m);
        float e3 = expf(kv.w - m);
        z += (e0 + e1) + (e2 + e3);
#pragma unroll
        for (int v = 0; v < 64; ++v) {
            float4 vv = *(const float4*)(vb + (size_t)v * NPIX + i);
            acc[v] += e0 * vv.x + e1 * vv.y + e2 * vv.z + e3 * vv.w;
        }
    }

    red[tid] = z;
    __syncthreads();
    for (int st = 128; st > 0; st >>= 1) {
        if (tid < st) red[tid] += red[tid + st];
        __syncthreads();
    }
    z = red[0];
    __syncthreads();
    const float invz = 1.0f / z;

    __shared__ float part[64][8];
#pragma unroll
    for (int v = 0; v < 64; ++v) {
        float xv = acc[v];
#pragma unroll
        for (int o = 16; o > 0; o >>= 1) xv += __shfl_down_sync(0xffffffffu, xv, o);
        if (lane == 0) part[v][wrp] = xv;
    }
    __syncthreads();
    if (tid < 64) {
        float sum = 0.f;
#pragma unroll
        for (int i = 0; i < 8; ++i) sum += part[tid][i];
        g_lamc[((size_t)b * 16 + kc) * 64 + tid] = g_sv[tid] * sum * invz + g_bv[tid];
    }
}

// ======================================================================
// K5: final fused output (UNCHANGED from R6 — protect the win).
// 512 threads = 64 pix x 8 v-groups (8 v each); all 4 heads per thread.
// ======================================================================
#define VHPITCH 68
#define QP      68
#define SP      28   // s pitch per pixel: 7 tt * 4 heads

__global__ __launch_bounds__(512, 2)
void k_final(const float* __restrict__ R, float* __restrict__ out) {
    extern __shared__ float sm[];
    float* q_sm    = sm;                     // [64 pix][QP]             4352
    float* vh_sm   = q_sm + 64 * QP;         // [196 hpix][VHPITCH]     13328
    float* s_sm    = vh_sm + 196 * VHPITCH;  // [64 pix][SP]             1792
    float* lamc_sm = s_sm + 64 * SP;         // [16 k][64 v]             1024
    float* R_sm    = lamc_sm + 1024;         // [16 k][49 t]              784

    const int b   = blockIdx.z;
    const int tx0 = blockIdx.x * 8;
    const int ty0 = blockIdx.y * 8;
    const int tid = threadIdx.x;

    for (int i = tid; i < 784; i += 512)  R_sm[i]    = R[i];
    for (int i = tid; i < 1024; i += 512) lamc_sm[i] = g_lamc[(size_t)b * 1024 + i];

    {   // q tile with BN, transposed [pix][ch]
        const float* qb = g_q + (size_t)b * 64 * NPIX;
        for (int idx = tid; idx < 4096; idx += 512) {
            int ch = idx >> 6, lp = idx & 63;
            int ly = lp >> 3,  lx = lp & 7;
            float v = qb[(size_t)ch * NPIX + (ty0 + ly) * IMGW + tx0 + lx];
            q_sm[lp * QP + ch] = v * g_sq[ch] + g_bq[ch];
        }
    }
    {   // v halo 14x14 with BN + zero pad, [hpix][ch]
        const float* vb = g_v + (size_t)b * 64 * NPIX;
        for (int idx = tid; idx < 196 * 64; idx += 512) {
            int ch = idx / 196, hp = idx - ch * 196;
            int hy = hp / 14,   hx = hp - hy * 14;
            int gy = ty0 + hy - PADR, gx = tx0 + hx - PADR;
            float v = 0.f;
            if (gy >= 0 && gy < IMGH && gx >= 0 && gx < IMGW)
                v = vb[(size_t)ch * NPIX + gy * IMGW + gx] * g_sv[ch] + g_bv[ch];
            vh_sm[hp * VHPITCH + ch] = v;
        }
    }
    __syncthreads();

    const int g   = tid >> 6;        // group 0..7 : v channels g*8..g*8+7
    const int pix = tid & 63;
    const int py  = pix >> 3, px = pix & 7;
    const float* qrow = q_sm + pix * QP;
    float* srow = s_sm + pix * SP;

    float acc[4][8];
#pragma unroll
    for (int h = 0; h < 4; ++h)
#pragma unroll
        for (int vi = 0; vi < 8; ++vi) acc[h][vi] = 0.f;

    // ---- Yc term ----
#pragma unroll
    for (int kk0 = 0; kk0 < 16; kk0 += 4) {
        float4 qh[4];
#pragma unroll
        for (int h = 0; h < 4; ++h)
            qh[h] = *(const float4*)(qrow + h * 16 + kk0);
#pragma unroll
        for (int j = 0; j < 4; ++j) {
            const float* lrow = lamc_sm + (kk0 + j) * 64 + g * 8;
            float4 l0 = ((const float4*)lrow)[0];
            float4 l1 = ((const float4*)lrow)[1];
            float lv[8] = {l0.x, l0.y, l0.z, l0.w, l1.x, l1.y, l1.z, l1.w};
            float q0 = (j == 0) ? qh[0].x : (j == 1) ? qh[0].y : (j == 2) ? qh[0].z : qh[0].w;
            float q1 = (j == 0) ? qh[1].x : (j == 1) ? qh[1].y : (j == 2) ? qh[1].z : qh[1].w;
            float q2 = (j == 0) ? qh[2].x : (j == 1) ? qh[2].y : (j == 2) ? qh[2].z : qh[2].w;
            float q3 = (j == 0) ? qh[3].x : (j == 1) ? qh[3].y : (j == 2) ? qh[3].z : qh[3].w;
#pragma unroll
            for (int vi = 0; vi < 8; ++vi) {
                acc[0][vi] += q0 * lv[vi];
                acc[1][vi] += q1 * lv[vi];
                acc[2][vi] += q2 * lv[vi];
                acc[3][vi] += q3 * lv[vi];
            }
        }
    }

    // ---- Yp term ----
    const int hs   = g & 3;
    const int ttlo = (g >> 2) ? 4 : 0;
    const int tthi = (g >> 2) ? 7 : 4;

    for (int dy = 0; dy < RKS; ++dy) {
        __syncthreads();
        {   // s phase
            float4 qa  = *(const float4*)(qrow + hs * 16 + 0);
            float4 qb4 = *(const float4*)(qrow + hs * 16 + 4);
            float4 qc  = *(const float4*)(qrow + hs * 16 + 8);
            float4 qd  = *(const float4*)(qrow + hs * 16 + 12);
            float qk[16] = {qa.x, qa.y, qa.z, qa.w, qb4.x, qb4.y, qb4.z, qb4.w,
                            qc.x, qc.y, qc.z, qc.w, qd.x, qd.y, qd.z, qd.w};
            for (int tt = ttlo; tt < tthi; ++tt) {
                float s = 0.f;
#pragma unroll
                for (int kk = 0; kk < 16; ++kk) s += qk[kk] * R_sm[kk * TAPS + dy * RKS + tt];
                srow[tt * 4 + hs] = s;
            }
        }
        __syncthreads();

#pragma unroll
        for (int dx = 0; dx < RKS; ++dx) {
            const int hp = (py + dy) * 14 + (px + dx);
            const float4* vp = (const float4*)(vh_sm + hp * VHPITCH + g * 8);
            float4 v0 = vp[0], v1 = vp[1];
            float vv[8] = {v0.x, v0.y, v0.z, v0.w, v1.x, v1.y, v1.z, v1.w};
            float4 s4 = *(const float4*)(srow + dx * 4);
#pragma unroll
            for (int vi = 0; vi < 8; ++vi) {
                acc[0][vi] += s4.x * vv[vi];
                acc[1][vi] += s4.y * vv[vi];
                acc[2][vi] += s4.z * vv[vi];
                acc[3][vi] += s4.w * vv[vi];
            }
        }
    }

    // ---- store ----
    const size_t ob = (size_t)b * 256 * NPIX;
    const int gp = (ty0 + py) * IMGW + tx0 + px;
#pragma unroll
    for (int h = 0; h < 4; ++h)
#pragma unroll
        for (int vi = 0; vi < 8; ++vi)
            out[ob + (size_t)(h * 64 + g * 8 + vi) * NPIX + gp] = acc[h][vi];
}

// ======================================================================
extern "C" void kernel_launch(void* const* d_in, const int* in_sizes, int n_in,
                              void* d_out, int out_size) {
    const float* x       = (const float*)d_in[0];
    const float* Wq      = (const float*)d_in[1];
    const float* Wk      = (const float*)d_in[2];
    const float* Wv      = (const float*)d_in[3];
    const float* gamma_q = (const float*)d_in[4];
    const float* beta_q  = (const float*)d_in[5];
    const float* gamma_v = (const float*)d_in[6];
    const float* beta_v  = (const float*)d_in[7];
    const float* R       = (const float*)d_in[8];
    float* out = (float*)d_out;

    const int smemK5 = (64 * QP + 196 * VHPITCH + 64 * SP + 1024 + 784) * (int)sizeof(float);
    cudaFuncSetAttribute(k_final, cudaFuncAttributeMaxDynamicSharedMemorySize, smemK5);

    k_proj<<<dim3(NPIX / 128, BATCH), 256>>>(x, Wq, Wk, Wv);
    k_bnstats<<<128, 256>>>(gamma_q, beta_q, gamma_v, beta_v);
    k_lamc<<<BATCH * 16, 256>>>();
    k_final<<<dim3(8, 8, BATCH), 512, smemK5>>>(R, out);
}

// round 8
// speedup vs baseline: 1.1339x; 1.1339x over previous
#include <cuda_runtime.h>
#include <math.h>

// ---------------- problem constants ----------------
#define BATCH   16
#define CIN     256
#define IMGH    64
#define IMGW    64
#define NPIX    4096          // 64*64
#define HEADS   4
#define DK      16
#define DV      64
#define RKS     7
#define TAPS    49            // 7*7
#define PADR    3

typedef unsigned long long ull;

// packed f32x2 helpers (sm_100+ PTX; ptxas never auto-fuses these)
__device__ __forceinline__ ull pk2(float lo, float hi) {
    ull r; asm("mov.b64 %0, {%1, %2};" : "=l"(r) : "f"(lo), "f"(hi)); return r;
}
__device__ __forceinline__ void fma2(ull& d, ull a, ull b) {
    asm("fma.rn.f32x2 %0, %1, %2, %0;" : "+l"(d) : "l"(a), "l"(b));
}
__device__ __forceinline__ float2 upk2(ull v) {
    float2 f; asm("mov.b64 {%0, %1}, %2;" : "=f"(f.x), "=f"(f.y) : "l"(v)); return f;
}

// ---------------- device scratch (globals: allowed) ----------------
__device__ float g_q[BATCH * 64 * NPIX];   // raw q projections [b][ch=h*16+k][p]
__device__ float g_k[BATCH * 16 * NPIX];   // raw k projections [b][k][p]
__device__ float g_v[BATCH * 64 * NPIX];   // raw v projections [b][v][p]
__device__ float g_sq[64], g_bq[64];       // BN fold for q: y = x*s + b
__device__ float g_sv[64], g_bv[64];       // BN fold for v
__device__ float g_lamc[BATCH * 16 * 64];  // lambda_c [b][k][v]

// ======================================================================
// K1: fused projection GEMM with f32x2 packed FMAs. Per batch:
// Y[144,4096] = W[144,256] * X[256,4096]; rows 0..63 q, 64..79 k, 80..143 v.
// Thread (ty,tx) owns rows ty+16i and pixels {tx*4..+3} U {64+tx*4..+3}
// (conflict-free LDS.128 phases). Inner: 9 packs + 36 FFMA2 per cc.
// ======================================================================
__global__ __launch_bounds__(256)
void k_proj(const float* __restrict__ x,
            const float* __restrict__ Wq,
            const float* __restrict__ Wk,
            const float* __restrict__ Wv) {
    __shared__ __align__(16) float Xs[16][128];
    __shared__ __align__(16) float Ws[144][17];

    const int b   = blockIdx.y;
    const int p0  = blockIdx.x * 128;
    const int tid = threadIdx.x;
    const int ty  = tid >> 4;    // 0..15 row group
    const int tx  = tid & 15;    // 0..15 -> pixels tx*4..+3 and 64+tx*4..+3

    const float* xb = x + (size_t)b * CIN * NPIX;

    ull acc2[9][4];              // [row i][pair: 2 for quad A, 2 for quad B]
#pragma unroll
    for (int i = 0; i < 9; ++i)
#pragma unroll
        for (int p = 0; p < 4; ++p) acc2[i][p] = 0ull;

    for (int c0 = 0; c0 < CIN; c0 += 16) {
#pragma unroll
        for (int r = 0; r < 8; ++r) {
            int idx = tid + r * 256;
            Xs[idx >> 7][idx & 127] = xb[(size_t)(c0 + (idx >> 7)) * NPIX + p0 + (idx & 127)];
        }
#pragma unroll
        for (int r = 0; r < 9; ++r) {
            int idx = tid + r * 256;
            int o = idx >> 4, cc = idx & 15;
            float w;
            if (o < 64)       w = Wq[o * CIN + c0 + cc];
            else if (o < 80)  w = Wk[(o - 64) * CIN + c0 + cc];
            else              w = Wv[(o - 80) * CIN + c0 + cc];
            Ws[o][cc] = w;
        }
        __syncthreads();

#pragma unroll
        for (int cc = 0; cc < 16; ++cc) {
            ulonglong2 xa = *(const ulonglong2*)&Xs[cc][tx * 4];
            ulonglong2 xbq = *(const ulonglong2*)&Xs[cc][64 + tx * 4];
#pragma unroll
            for (int i = 0; i < 9; ++i) {
                float a = Ws[ty + 16 * i][cc];
                ull ap = pk2(a, a);
                fma2(acc2[i][0], ap, xa.x);
                fma2(acc2[i][1], ap, xa.y);
                fma2(acc2[i][2], ap, xbq.x);
                fma2(acc2[i][3], ap, xbq.y);
            }
        }
        __syncthreads();
    }

    // ---- store: 2x STG.128 per row ----
#pragma unroll
    for (int i = 0; i < 9; ++i) {
        int o = ty + 16 * i;
        float* dst;
        if (o < 64)      dst = g_q + ((size_t)b * 64 + o) * NPIX;
        else if (o < 80) dst = g_k + ((size_t)b * 16 + (o - 64)) * NPIX;
        else             dst = g_v + ((size_t)b * 64 + (o - 80)) * NPIX;
        float2 f0 = upk2(acc2[i][0]), f1 = upk2(acc2[i][1]);
        float2 f2 = upk2(acc2[i][2]), f3 = upk2(acc2[i][3]);
        *(float4*)(dst + p0 + tx * 4)      = make_float4(f0.x, f0.y, f1.x, f1.y);
        *(float4*)(dst + p0 + 64 + tx * 4) = make_float4(f2.x, f2.y, f3.x, f3.y);
    }
}

// ======================================================================
// K2: BN statistics -> folded scale/bias. 128 blocks. (R6 version)
// ======================================================================
__global__ __launch_bounds__(256)
void k_bnstats(const float* __restrict__ gamma_q, const float* __restrict__ beta_q,
               const float* __restrict__ gamma_v, const float* __restrict__ beta_v) {
    const int ch  = blockIdx.x;
    const int tid = threadIdx.x;

    const float* src;
    float gamma, beta;
    float *sdst, *bdst;
    if (ch < 64) {
        src = g_q + (size_t)ch * NPIX;
        gamma = gamma_q[ch]; beta = beta_q[ch];
        sdst = &g_sq[ch]; bdst = &g_bq[ch];
    } else {
        int c = ch - 64;
        src = g_v + (size_t)c * NPIX;
        gamma = gamma_v[c]; beta = beta_v[c];
        sdst = &g_sv[c]; bdst = &g_bv[c];
    }

    float s = 0.f, s2 = 0.f;
    for (int b = 0; b < BATCH; ++b) {
        const float* p = src + (size_t)b * 64 * NPIX;
        for (int i = tid; i < NPIX; i += 256) {
            float v = p[i];
            s  += v;
            s2 += v * v;
        }
    }
    __shared__ float ss[256], ss2[256];
    ss[tid] = s; ss2[tid] = s2;
    __syncthreads();
    for (int st = 128; st > 0; st >>= 1) {
        if (tid < st) { ss[tid] += ss[tid + st]; ss2[tid] += ss2[tid + st]; }
        __syncthreads();
    }
    if (tid == 0) {
        const float inv_n = 1.0f / 65536.0f;
        float mean = ss[0] * inv_n;
        float var  = ss2[0] * inv_n - mean * mean;
        float sc   = gamma * rsqrtf(var + 1e-5f);
        *sdst = sc;
        *bdst = beta - mean * sc;
    }
}

// ======================================================================
// K3: softmax over k row + lambda_c, fused. One block per (b, k). (R6 version)
// ======================================================================
__global__ __launch_bounds__(256)
void k_lamc() {
    const int bk  = blockIdx.x;
    const int b   = bk >> 4;
    const int kc  = bk & 15;
    const int tid = threadIdx.x;
    const int lane = tid & 31, wrp = tid >> 5;

    const float* krow = g_k + ((size_t)b * 16 + kc) * NPIX;
    const float* vb   = g_v + (size_t)b * 64 * NPIX;

    __shared__ float red[256];

    float m = -1e30f;
    for (int i = tid; i < NPIX; i += 256) m = fmaxf(m, krow[i]);
    red[tid] = m;
    __syncthreads();
    for (int st = 128; st > 0; st >>= 1) {
        if (tid < st) red[tid] = fmaxf(red[tid], red[tid + st]);
        __syncthreads();
    }
    m = red[0];
    __syncthreads();

    float acc[64];
#pragma unroll
    for (int v = 0; v < 64; ++v) acc[v] = 0.f;
    float z = 0.f;

    for (int i = tid; i < NPIX; i += 256) {
        float w = expf(krow[i] - m);
        z += w;
#pragma unroll
        for (int v = 0; v < 64; ++v) acc[v] += w * vb[(size_t)v * NPIX + i];
    }

    red[tid] = z;
    __syncthreads();
    for (int st = 128; st > 0; st >>= 1) {
        if (tid < st) red[tid] += red[tid + st];
        __syncthreads();
    }
    z = red[0];
    __syncthreads();
    const float invz = 1.0f / z;

    __shared__ float part[64][8];
#pragma unroll
    for (int v = 0; v < 64; ++v) {
        float xv = acc[v];
#pragma unroll
        for (int o = 16; o > 0; o >>= 1) xv += __shfl_down_sync(0xffffffffu, xv, o);
        if (lane == 0) part[v][wrp] = xv;
    }
    __syncthreads();
    if (tid < 64) {
        float sum = 0.f;
#pragma unroll
        for (int i = 0; i < 8; ++i) sum += part[tid][i];
        g_lamc[((size_t)b * 16 + kc) * 64 + tid] = g_sv[tid] * sum * invz + g_bv[tid];
    }
}

// ======================================================================
// K5: final fused output with f32x2 packed FMAs.
// 512 threads = 64 pix x 8 v-groups (8 v each); all 4 heads per thread.
// acc2[4][4] u64 pairs; vv pairs free from LDS.128; s/q broadcast packed.
// ======================================================================
#define VHPITCH 68
#define QP      68
#define SP      28   // s pitch per pixel: 7 tt * 4 heads

__global__ __launch_bounds__(512, 2)
void k_final(const float* __restrict__ R, float* __restrict__ out) {
    extern __shared__ float sm[];
    float* q_sm    = sm;                     // [64 pix][QP]             4352
    float* vh_sm   = q_sm + 64 * QP;         // [196 hpix][VHPITCH]     13328
    float* s_sm    = vh_sm + 196 * VHPITCH;  // [64 pix][SP]             1792
    float* lamc_sm = s_sm + 64 * SP;         // [16 k][64 v]             1024
    float* R_sm    = lamc_sm + 1024;         // [16 k][49 t]              784

    const int b   = blockIdx.z;
    const int tx0 = blockIdx.x * 8;
    const int ty0 = blockIdx.y * 8;
    const int tid = threadIdx.x;

    for (int i = tid; i < 784; i += 512)  R_sm[i]    = R[i];
    for (int i = tid; i < 1024; i += 512) lamc_sm[i] = g_lamc[(size_t)b * 1024 + i];

    {   // q tile with BN, transposed [pix][ch]
        const float* qb = g_q + (size_t)b * 64 * NPIX;
        for (int idx = tid; idx < 4096; idx += 512) {
            int ch = idx >> 6, lp = idx & 63;
            int ly = lp >> 3,  lx = lp & 7;
            float v = qb[(size_t)ch * NPIX + (ty0 + ly) * IMGW + tx0 + lx];
            q_sm[lp * QP + ch] = v * g_sq[ch] + g_bq[ch];
        }
    }
    {   // v halo 14x14 with BN + zero pad, [hpix][ch]
        const float* vb = g_v + (size_t)b * 64 * NPIX;
        for (int idx = tid; idx < 196 * 64; idx += 512) {
            int ch = idx / 196, hp = idx - ch * 196;
            int hy = hp / 14,   hx = hp - hy * 14;
            int gy = ty0 + hy - PADR, gx = tx0 + hx - PADR;
            float v = 0.f;
            if (gy >= 0 && gy < IMGH && gx >= 0 && gx < IMGW)
                v = vb[(size_t)ch * NPIX + gy * IMGW + gx] * g_sv[ch] + g_bv[ch];
            vh_sm[hp * VHPITCH + ch] = v;
        }
    }
    __syncthreads();

    const int g   = tid >> 6;        // group 0..7 : v channels g*8..g*8+7
    const int pix = tid & 63;
    const int py  = pix >> 3, px = pix & 7;
    const float* qrow = q_sm + pix * QP;
    float* srow = s_sm + pix * SP;

    ull acc2[4][4];                  // [head][vi-pair]
#pragma unroll
    for (int h = 0; h < 4; ++h)
#pragma unroll
        for (int p = 0; p < 4; ++p) acc2[h][p] = 0ull;

    // ---- Yc term ----
#pragma unroll
    for (int kk0 = 0; kk0 < 16; kk0 += 4) {
        float4 qh[4];
#pragma unroll
        for (int h = 0; h < 4; ++h)
            qh[h] = *(const float4*)(qrow + h * 16 + kk0);
#pragma unroll
        for (int j = 0; j < 4; ++j) {
            const ulonglong2* l2 = (const ulonglong2*)(lamc_sm + (kk0 + j) * 64 + g * 8);
            ulonglong2 la = l2[0], lb = l2[1];
            float qs[4];
            qs[0] = (j == 0) ? qh[0].x : (j == 1) ? qh[0].y : (j == 2) ? qh[0].z : qh[0].w;
            qs[1] = (j == 0) ? qh[1].x : (j == 1) ? qh[1].y : (j == 2) ? qh[1].z : qh[1].w;
            qs[2] = (j == 0) ? qh[2].x : (j == 1) ? qh[2].y : (j == 2) ? qh[2].z : qh[2].w;
            qs[3] = (j == 0) ? qh[3].x : (j == 1) ? qh[3].y : (j == 2) ? qh[3].z : qh[3].w;
#pragma unroll
            for (int h = 0; h < 4; ++h) {
                ull qp = pk2(qs[h], qs[h]);
                fma2(acc2[h][0], qp, la.x);
                fma2(acc2[h][1], qp, la.y);
                fma2(acc2[h][2], qp, lb.x);
                fma2(acc2[h][3], qp, lb.y);
            }
        }
    }

    // ---- Yp term: dy row-groups of the 7x7 stencil ----
    const int hs   = g & 3;
    const int ttlo = (g >> 2) ? 4 : 0;
    const int tthi = (g >> 2) ? 7 : 4;

    for (int dy = 0; dy < RKS; ++dy) {
        __syncthreads();
        {   // s phase
            float4 qa  = *(const float4*)(qrow + hs * 16 + 0);
            float4 qb4 = *(const float4*)(qrow + hs * 16 + 4);
            float4 qc  = *(const float4*)(qrow + hs * 16 + 8);
            float4 qd  = *(const float4*)(qrow + hs * 16 + 12);
            float qk[16] = {qa.x, qa.y, qa.z, qa.w, qb4.x, qb4.y, qb4.z, qb4.w,
                            qc.x, qc.y, qc.z, qc.w, qd.x, qd.y, qd.z, qd.w};
            for (int tt = ttlo; tt < tthi; ++tt) {
                float s = 0.f;
#pragma unroll
                for (int kk = 0; kk < 16; ++kk) s += qk[kk] * R_sm[kk * TAPS + dy * RKS + tt];
                srow[tt * 4 + hs] = s;
            }
        }
        __syncthreads();

#pragma unroll
        for (int dx = 0; dx < RKS; ++dx) {
            const int hp = (py + dy) * 14 + (px + dx);
            const ulonglong2* vp = (const ulonglong2*)(vh_sm + hp * VHPITCH + g * 8);
            ulonglong2 va = vp[0], vb2 = vp[1];
            float4 s4 = *(const float4*)(srow + dx * 4);   // heads 0..3
            ull sp0 = pk2(s4.x, s4.x);
            ull sp1 = pk2(s4.y, s4.y);
            ull sp2 = pk2(s4.z, s4.z);
            ull sp3 = pk2(s4.w, s4.w);
            fma2(acc2[0][0], sp0, va.x); fma2(acc2[0][1], sp0, va.y);
            fma2(acc2[0][2], sp0, vb2.x); fma2(acc2[0][3], sp0, vb2.y);
            fma2(acc2[1][0], sp1, va.x); fma2(acc2[1][1], sp1, va.y);
            fma2(acc2[1][2], sp1, vb2.x); fma2(acc2[1][3], sp1, vb2.y);
            fma2(acc2[2][0], sp2, va.x); fma2(acc2[2][1], sp2, va.y);
            fma2(acc2[2][2], sp2, vb2.x); fma2(acc2[2][3], sp2, vb2.y);
            fma2(acc2[3][0], sp3, va.x); fma2(acc2[3][1], sp3, va.y);
            fma2(acc2[3][2], sp3, vb2.x); fma2(acc2[3][3], sp3, vb2.y);
        }
    }

    // ---- store: out channel = h*64 + g*8 + vi ----
    const size_t ob = (size_t)b * 256 * NPIX;
    const int gp = (ty0 + py) * IMGW + tx0 + px;
#pragma unroll
    for (int h = 0; h < 4; ++h) {
        float* dsth = out + ob + (size_t)(h * 64 + g * 8) * NPIX + gp;
#pragma unroll
        for (int p = 0; p < 4; ++p) {
            float2 f = upk2(acc2[h][p]);
            dsth[(size_t)(2 * p) * NPIX]     = f.x;
            dsth[(size_t)(2 * p + 1) * NPIX] = f.y;
        }
    }
}

// ======================================================================
extern "C" void kernel_launch(void* const* d_in, const int* in_sizes, int n_in,
                              void* d_out, int out_size) {
    const float* x       = (const float*)d_in[0];
    const float* Wq      = (const float*)d_in[1];
    const float* Wk      = (const float*)d_in[2];
    const float* Wv      = (const float*)d_in[3];
    const float* gamma_q = (const float*)d_in[4];
    const float* beta_q  = (const float*)d_in[5];
    const float* gamma_v = (const float*)d_in[6];
    const float* beta_v  = (const float*)d_in[7];
    const float* R       = (const float*)d_in[8];
    float* out = (float*)d_out;

    const int smemK5 = (64 * QP + 196 * VHPITCH + 64 * SP + 1024 + 784) * (int)sizeof(float);
    cudaFuncSetAttribute(k_final, cudaFuncAttributeMaxDynamicSharedMemorySize, smemK5);

    k_proj<<<dim3(NPIX / 128, BATCH), 256>>>(x, Wq, Wk, Wv);
    k_bnstats<<<128, 256>>>(gamma_q, beta_q, gamma_v, beta_v);
    k_lamc<<<BATCH * 16, 256>>>();
    k_final<<<dim3(8, 8, BATCH), 512, smemK5>>>(R, out);
}

// round 10
// speedup vs baseline: 1.5146x; 1.3357x over previous
#include <cuda_runtime.h>
#include <cuda_bf16.h>
#include <math.h>

// ---------------- problem constants ----------------
#define BATCH   16
#define CIN     256
#define IMGH    64
#define IMGW    64
#define NPIX    4096
#define HEADS   4
#define DK      16
#define DV      64
#define RKS     7
#define TAPS    49
#define PADR    3

#define N_OUT   144        // 64 q + 16 k + 64 v
#define MT      128        // pixels per CTA tile
#define KCH     64         // K-chunk staged per iteration

// smem byte offsets for k_proj (A: [k][pix] bf16, B: [out][k] bf16)
#define PITCH_A 272        // 128 bf16 (256B) + 16B pad -> 68 words === 4 mod 32
#define PITCH_B 144        // 64 bf16 (128B) + 16B pad  -> 36 words === 4 mod 32
#define OFF_AHI 0
#define OFF_ALO (OFF_AHI + KCH * PITCH_A)        // 17408
#define OFF_BHI (OFF_ALO + KCH * PITCH_A)        // 34816
#define OFF_BLO (OFF_BHI + N_OUT * PITCH_B)      // 55552
#define SM_PROJ (OFF_BLO + N_OUT * PITCH_B)      // 76288  (D reuse: 144*132*4=76032)
#define DPITCH  132        // f32 words per output row in epilogue smem

// ---------------- device scratch ----------------
__device__ float g_q[BATCH * 64 * NPIX];
__device__ float g_k[BATCH * 16 * NPIX];
__device__ float g_v[BATCH * 64 * NPIX];
__device__ float g_sq[64], g_bq[64];
__device__ float g_sv[64], g_bv[64];
__device__ float g_lamc[BATCH * 16 * 64];

// ---------------- helpers ----------------
__device__ __forceinline__ unsigned smem_u32(const void* p) {
    unsigned a;
    asm("{ .reg .u64 t; cvta.to.shared.u64 t, %1; cvt.u32.u64 %0, t; }" : "=r"(a) : "l"(p));
    return a;
}
__device__ __forceinline__ void ldsm_x4t(unsigned addr, unsigned& r0, unsigned& r1,
                                         unsigned& r2, unsigned& r3) {
    asm volatile("ldmatrix.sync.aligned.m8n8.x4.trans.shared.b16 {%0,%1,%2,%3}, [%4];"
                 : "=r"(r0), "=r"(r1), "=r"(r2), "=r"(r3) : "r"(addr));
}
__device__ __forceinline__ void ldsm_x2(unsigned addr, unsigned& r0, unsigned& r1) {
    asm volatile("ldmatrix.sync.aligned.m8n8.x2.shared.b16 {%0,%1}, [%2];"
                 : "=r"(r0), "=r"(r1) : "r"(addr));
}
__device__ __forceinline__ void mma16816(float* d, const unsigned* a, unsigned b0, unsigned b1) {
    asm volatile(
        "mma.sync.aligned.m16n8k16.row.col.f32.bf16.bf16.f32 "
        "{%0,%1,%2,%3}, {%4,%5,%6,%7}, {%8,%9}, {%0,%1,%2,%3};"
        : "+f"(d[0]), "+f"(d[1]), "+f"(d[2]), "+f"(d[3])
        : "r"(a[0]), "r"(a[1]), "r"(a[2]), "r"(a[3]), "r"(b0), "r"(b1));
}
// split f into bf16 hi + bf16 lo (residual)
__device__ __forceinline__ void bf_split(float f, unsigned short& hi, unsigned short& lo) {
    __nv_bfloat16 h = __float2bfloat16_rn(f);
    __nv_bfloat16 l = __float2bfloat16_rn(f - __bfloat162float(h));
    hi = __bfloat16_as_ushort(h);
    lo = __bfloat16_as_ushort(l);
}

// ======================================================================
// K1: projection via mma.sync bf16 2-way split (HMMA; plain PTX, sm_80+).
// D[pix=128, out=144] per CTA; K=256 in 4 chunks of 64.
// 256 thr = 8 warps: 4 (M) x 2 (N); warp tile 32 pix x 72 out.
// acc += Ahi*Bhi + Ahi*Blo + Alo*Bhi  (all into same fp32 acc).
// ======================================================================
__global__ __launch_bounds__(256)
void k_proj(const float* __restrict__ x,
            const float* __restrict__ Wq,
            const float* __restrict__ Wk,
            const float* __restrict__ Wv) {
    extern __shared__ __align__(16) char smem[];
    const unsigned sb = smem_u32(smem);
    const int tid  = threadIdx.x;
    const int lane = tid & 31;
    const int wid  = tid >> 5;
    const int wm   = wid & 3;     // M warp: pixels wm*32..+31
    const int wn   = wid >> 2;    // N warp: outputs wn*72..+71
    const int b    = blockIdx.y;
    const int pix0 = blockIdx.x * MT;

    const float* xb = x + (size_t)b * CIN * NPIX + pix0;

    float acc[2][9][4];
#pragma unroll
    for (int mi = 0; mi < 2; ++mi)
#pragma unroll
        for (int ni = 0; ni < 9; ++ni)
#pragma unroll
            for (int r = 0; r < 4; ++r) acc[mi][ni][r] = 0.f;

    // lane components for ldmatrix addresses
    const int a_kl = (lane & 7) + ((lane >> 4) << 3);   // k row within 16
    const int a_pl = ((lane >> 3) & 1) * 8;             // pix col offset
    const int l15  = lane & 15;
    const int b_nl = l15 & 7;                           // out row within 8
    const int b_kl = ((l15 >> 3) & 1) * 8;              // k col offset

    for (int chunk = 0; chunk < 4; ++chunk) {
        const int c0 = chunk * KCH;

        // ---- stage A: X[c0+cc][pix] -> As[cc][pp] bf16 hi/lo ----
#pragma unroll
        for (int i = 0; i < 16; ++i) {
            int idx = tid + i * 256;            // 0..4095
            int cc = idx >> 6, pq = idx & 63;   // pp = pq*2
            float2 xv = *(const float2*)(xb + (size_t)(c0 + cc) * NPIX + pq * 2);
            unsigned short h0, l0, h1, l1;
            bf_split(xv.x, h0, l0);
            bf_split(xv.y, h1, l1);
            *(unsigned*)(smem + OFF_AHI + cc * PITCH_A + pq * 4) = (unsigned)h0 | ((unsigned)h1 << 16);
            *(unsigned*)(smem + OFF_ALO + cc * PITCH_A + pq * 4) = (unsigned)l0 | ((unsigned)l1 << 16);
        }
        // ---- stage B: W[o][c0+k] -> Bs[o][k] bf16 hi/lo ----
#pragma unroll
        for (int i = 0; i < 18; ++i) {
            int idx = tid + i * 256;            // 0..4607
            int o = idx >> 5, kq = idx & 31;    // k = kq*2
            const float* wrow = (o < 64) ? (Wq + o * CIN)
                              : (o < 80) ? (Wk + (o - 64) * CIN)
                                         : (Wv + (o - 80) * CIN);
            float2 wv = *(const float2*)(wrow + c0 + kq * 2);
            unsigned short h0, l0, h1, l1;
            bf_split(wv.x, h0, l0);
            bf_split(wv.y, h1, l1);
            *(unsigned*)(smem + OFF_BHI + o * PITCH_B + kq * 4) = (unsigned)h0 | ((unsigned)h1 << 16);
            *(unsigned*)(smem + OFF_BLO + o * PITCH_B + kq * 4) = (unsigned)l0 | ((unsigned)l1 << 16);
        }
        __syncthreads();

        // ---- MMA over 4 k16 steps ----
#pragma unroll
        for (int ks = 0; ks < 4; ++ks) {
            unsigned ahi[2][4], alo[2][4];
#pragma unroll
            for (int mi = 0; mi < 2; ++mi) {
                unsigned aoff = (unsigned)((ks * 16 + a_kl) * PITCH_A
                                           + (wm * 32 + mi * 16 + a_pl) * 2);
                ldsm_x4t(sb + OFF_AHI + aoff, ahi[mi][0], ahi[mi][1], ahi[mi][2], ahi[mi][3]);
                ldsm_x4t(sb + OFF_ALO + aoff, alo[mi][0], alo[mi][1], alo[mi][2], alo[mi][3]);
            }
#pragma unroll
            for (int ni = 0; ni < 9; ++ni) {
                unsigned boff = (unsigned)((wn * 72 + ni * 8 + b_nl) * PITCH_B
                                           + (ks * 16 + b_kl) * 2);
                unsigned bh0, bh1, bl0, bl1;
                ldsm_x2(sb + OFF_BHI + boff, bh0, bh1);
                ldsm_x2(sb + OFF_BLO + boff, bl0, bl1);
#pragma unroll
                for (int mi = 0; mi < 2; ++mi) {
                    mma16816(acc[mi][ni], ahi[mi], bh0, bh1);
                    mma16816(acc[mi][ni], ahi[mi], bl0, bl1);
                    mma16816(acc[mi][ni], alo[mi], bh0, bh1);
                }
            }
        }
        __syncthreads();
    }

    // ---- epilogue: fragments -> smem D[o][pix] -> coalesced global ----
    float* dsm = (float*)smem;
    {
#pragma unroll
        for (int mi = 0; mi < 2; ++mi)
#pragma unroll
            for (int ni = 0; ni < 9; ++ni) {
                int o = wn * 72 + ni * 8 + (lane & 3) * 2;
                int p = wm * 32 + mi * 16 + (lane >> 2);
                dsm[o * DPITCH + p]           = acc[mi][ni][0];   // (p,   o)
                dsm[(o + 1) * DPITCH + p]     = acc[mi][ni][1];   // (p,   o+1)
                dsm[o * DPITCH + p + 8]       = acc[mi][ni][2];   // (p+8, o)
                dsm[(o + 1) * DPITCH + p + 8] = acc[mi][ni][3];   // (p+8, o+1)
            }
    }
    __syncthreads();

    float* qd = g_q + (size_t)b * 64 * NPIX;
    float* kd = g_k + (size_t)b * 16 * NPIX;
    float* vd = g_v + (size_t)b * 64 * NPIX;
#pragma unroll
    for (int i = 0; i < 18; ++i) {
        int idx = tid + i * 256;            // 0..4607 float4 units
        int o = idx >> 5, p4 = idx & 31;
        float4 val = *(const float4*)(dsm + o * DPITCH + p4 * 4);
        float* dst;
        if (o < 64)      dst = qd + (size_t)o * NPIX;
        else if (o < 80) dst = kd + (size_t)(o - 64) * NPIX;
        else             dst = vd + (size_t)(o - 80) * NPIX;
        *(float4*)(dst + pix0 + p4 * 4) = val;
    }
}

// ======================================================================
// K2: BN statistics -> folded scale/bias. (R6 version)
// ======================================================================
__global__ __launch_bounds__(256)
void k_bnstats(const float* __restrict__ gamma_q, const float* __restrict__ beta_q,
               const float* __restrict__ gamma_v, const float* __restrict__ beta_v) {
    const int ch  = blockIdx.x;
    const int tid = threadIdx.x;

    const float* src;
    float gamma, beta;
    float *sdst, *bdst;
    if (ch < 64) {
        src = g_q + (size_t)ch * NPIX;
        gamma = gamma_q[ch]; beta = beta_q[ch];
        sdst = &g_sq[ch]; bdst = &g_bq[ch];
    } else {
        int c = ch - 64;
        src = g_v + (size_t)c * NPIX;
        gamma = gamma_v[c]; beta = beta_v[c];
        sdst = &g_sv[c]; bdst = &g_bv[c];
    }

    float s = 0.f, s2 = 0.f;
    for (int b = 0; b < BATCH; ++b) {
        const float* p = src + (size_t)b * 64 * NPIX;
        for (int i = tid; i < NPIX; i += 256) {
            float v = p[i];
            s  += v;
            s2 += v * v;
        }
    }
    __shared__ float ss[256], ss2[256];
    ss[tid] = s; ss2[tid] = s2;
    __syncthreads();
    for (int st = 128; st > 0; st >>= 1) {
        if (tid < st) { ss[tid] += ss[tid + st]; ss2[tid] += ss2[tid + st]; }
        __syncthreads();
    }
    if (tid == 0) {
        const float inv_n = 1.0f / 65536.0f;
        float mean = ss[0] * inv_n;
        float var  = ss2[0] * inv_n - mean * mean;
        float sc   = gamma * rsqrtf(var + 1e-5f);
        *sdst = sc;
        *bdst = beta - mean * sc;
    }
}

// ======================================================================
// K3: softmax + lambda_c. (R6 version)
// ======================================================================
__global__ __launch_bounds__(256)
void k_lamc() {
    const int bk  = blockIdx.x;
    const int b   = bk >> 4;
    const int kc  = bk & 15;
    const int tid = threadIdx.x;
    const int lane = tid & 31, wrp = tid >> 5;

    const float* krow = g_k + ((size_t)b * 16 + kc) * NPIX;
    const float* vb   = g_v + (size_t)b * 64 * NPIX;

    __shared__ float red[256];

    float m = -1e30f;
    for (int i = tid; i < NPIX; i += 256) m = fmaxf(m, krow[i]);
    red[tid] = m;
    __syncthreads();
    for (int st = 128; st > 0; st >>= 1) {
        if (tid < st) red[tid] = fmaxf(red[tid], red[tid + st]);
        __syncthreads();
    }
    m = red[0];
    __syncthreads();

    float acc[64];
#pragma unroll
    for (int v = 0; v < 64; ++v) acc[v] = 0.f;
    float z = 0.f;

    for (int i = tid; i < NPIX; i += 256) {
        float w = expf(krow[i] - m);
        z += w;
#pragma unroll
        for (int v = 0; v < 64; ++v) acc[v] += w * vb[(size_t)v * NPIX + i];
    }

    red[tid] = z;
    __syncthreads();
    for (int st = 128; st > 0; st >>= 1) {
        if (tid < st) red[tid] += red[tid + st];
        __syncthreads();
    }
    z = red[0];
    __syncthreads();
    const float invz = 1.0f / z;

    __shared__ float part[64][8];
#pragma unroll
    for (int v = 0; v < 64; ++v) {
        float xv = acc[v];
#pragma unroll
        for (int o = 16; o > 0; o >>= 1) xv += __shfl_down_sync(0xffffffffu, xv, o);
        if (lane == 0) part[v][wrp] = xv;
    }
    __syncthreads();
    if (tid < 64) {
        float sum = 0.f;
#pragma unroll
        for (int i = 0; i < 8; ++i) sum += part[tid][i];
        g_lamc[((size_t)b * 16 + kc) * 64 + tid] = g_sv[tid] * sum * invz + g_bv[tid];
    }
}

// ======================================================================
// K5: final fused output (R6 version — best known).
// ======================================================================
#define VHPITCH 68
#define QP      68
#define SP      28

__global__ __launch_bounds__(512, 2)
void k_final(const float* __restrict__ R, float* __restrict__ out) {
    extern __shared__ float sm[];
    float* q_sm    = sm;
    float* vh_sm   = q_sm + 64 * QP;
    float* s_sm    = vh_sm + 196 * VHPITCH;
    float* lamc_sm = s_sm + 64 * SP;
    float* R_sm    = lamc_sm + 1024;

    const int b   = blockIdx.z;
    const int tx0 = blockIdx.x * 8;
    const int ty0 = blockIdx.y * 8;
    const int tid = threadIdx.x;

    for (int i = tid; i < 784; i += 512)  R_sm[i]    = R[i];
    for (int i = tid; i < 1024; i += 512) lamc_sm[i] = g_lamc[(size_t)b * 1024 + i];

    {
        const float* qb = g_q + (size_t)b * 64 * NPIX;
        for (int idx = tid; idx < 4096; idx += 512) {
            int ch = idx >> 6, lp = idx & 63;
            int ly = lp >> 3,  lx = lp & 7;
            float v = qb[(size_t)ch * NPIX + (ty0 + ly) * IMGW + tx0 + lx];
            q_sm[lp * QP + ch] = v * g_sq[ch] + g_bq[ch];
        }
    }
    {
        const float* vb = g_v + (size_t)b * 64 * NPIX;
        for (int idx = tid; idx < 196 * 64; idx += 512) {
            int ch = idx / 196, hp = idx - ch * 196;
            int hy = hp / 14,   hx = hp - hy * 14;
            int gy = ty0 + hy - PADR, gx = tx0 + hx - PADR;
            float v = 0.f;
            if (gy >= 0 && gy < IMGH && gx >= 0 && gx < IMGW)
                v = vb[(size_t)ch * NPIX + gy * IMGW + gx] * g_sv[ch] + g_bv[ch];
            vh_sm[hp * VHPITCH + ch] = v;
        }
    }
    __syncthreads();

    const int g   = tid >> 6;
    const int pix = tid & 63;
    const int py  = pix >> 3, px = pix & 7;
    const float* qrow = q_sm + pix * QP;
    float* srow = s_sm + pix * SP;

    float acc[4][8];
#pragma unroll
    for (int h = 0; h < 4; ++h)
#pragma unroll
        for (int vi = 0; vi < 8; ++vi) acc[h][vi] = 0.f;

#pragma unroll
    for (int kk0 = 0; kk0 < 16; kk0 += 4) {
        float4 qh[4];
#pragma unroll
        for (int h = 0; h < 4; ++h)
            qh[h] = *(const float4*)(qrow + h * 16 + kk0);
#pragma unroll
        for (int j = 0; j < 4; ++j) {
            const float* lrow = lamc_sm + (kk0 + j) * 64 + g * 8;
            float4 l0 = ((const float4*)lrow)[0];
            float4 l1 = ((const float4*)lrow)[1];
            float lv[8] = {l0.x, l0.y, l0.z, l0.w, l1.x, l1.y, l1.z, l1.w};
            float q0 = (j == 0) ? qh[0].x : (j == 1) ? qh[0].y : (j == 2) ? qh[0].z : qh[0].w;
            float q1 = (j == 0) ? qh[1].x : (j == 1) ? qh[1].y : (j == 2) ? qh[1].z : qh[1].w;
            float q2 = (j == 0) ? qh[2].x : (j == 1) ? qh[2].y : (j == 2) ? qh[2].z : qh[2].w;
            float q3 = (j == 0) ? qh[3].x : (j == 1) ? qh[3].y : (j == 2) ? qh[3].z : qh[3].w;
#pragma unroll
            for (int vi = 0; vi < 8; ++vi) {
                acc[0][vi] += q0 * lv[vi];
                acc[1][vi] += q1 * lv[vi];
                acc[2][vi] += q2 * lv[vi];
                acc[3][vi] += q3 * lv[vi];
            }
        }
    }

    const int hs   = g & 3;
    const int ttlo = (g >> 2) ? 4 : 0;
    const int tthi = (g >> 2) ? 7 : 4;

    for (int dy = 0; dy < RKS; ++dy) {
        __syncthreads();
        {
            float4 qa  = *(const float4*)(qrow + hs * 16 + 0);
            float4 qb4 = *(const float4*)(qrow + hs * 16 + 4);
            float4 qc  = *(const float4*)(qrow + hs * 16 + 8);
            float4 qd  = *(const float4*)(qrow + hs * 16 + 12);
            float qk[16] = {qa.x, qa.y, qa.z, qa.w, qb4.x, qb4.y, qb4.z, qb4.w,
                            qc.x, qc.y, qc.z, qc.w, qd.x, qd.y, qd.z, qd.w};
            for (int tt = ttlo; tt < tthi; ++tt) {
                float s = 0.f;
#pragma unroll
                for (int kk = 0; kk < 16; ++kk) s += qk[kk] * R_sm[kk * TAPS + dy * RKS + tt];
                srow[tt * 4 + hs] = s;
            }
        }
        __syncthreads();

#pragma unroll
        for (int dx = 0; dx < RKS; ++dx) {
            const int hp = (py + dy) * 14 + (px + dx);
            const float4* vp = (const float4*)(vh_sm + hp * VHPITCH + g * 8);
            float4 v0 = vp[0], v1 = vp[1];
            float vv[8] = {v0.x, v0.y, v0.z, v0.w, v1.x, v1.y, v1.z, v1.w};
            float4 s4 = *(const float4*)(srow + dx * 4);
#pragma unroll
            for (int vi = 0; vi < 8; ++vi) {
                acc[0][vi] += s4.x * vv[vi];
                acc[1][vi] += s4.y * vv[vi];
                acc[2][vi] += s4.z * vv[vi];
                acc[3][vi] += s4.w * vv[vi];
            }
        }
    }

    const size_t ob = (size_t)b * 256 * NPIX;
    const int gp = (ty0 + py) * IMGW + tx0 + px;
#pragma unroll
    for (int h = 0; h < 4; ++h)
#pragma unroll
        for (int vi = 0; vi < 8; ++vi)
            out[ob + (size_t)(h * 64 + g * 8 + vi) * NPIX + gp] = acc[h][vi];
}

// ======================================================================
extern "C" void kernel_launch(void* const* d_in, const int* in_sizes, int n_in,
                              void* d_out, int out_size) {
    const float* x       = (const float*)d_in[0];
    const float* Wq      = (const float*)d_in[1];
    const float* Wk      = (const float*)d_in[2];
    const float* Wv      = (const float*)d_in[3];
    const float* gamma_q = (const float*)d_in[4];
    const float* beta_q  = (const float*)d_in[5];
    const float* gamma_v = (const float*)d_in[6];
    const float* beta_v  = (const float*)d_in[7];
    const float* R       = (const float*)d_in[8];
    float* out = (float*)d_out;

    cudaFuncSetAttribute(k_proj, cudaFuncAttributeMaxDynamicSharedMemorySize, SM_PROJ);
    const int smemK5 = (64 * QP + 196 * VHPITCH + 64 * SP + 1024 + 784) * (int)sizeof(float);
    cudaFuncSetAttribute(k_final, cudaFuncAttributeMaxDynamicSharedMemorySize, smemK5);

    k_proj<<<dim3(NPIX / MT, BATCH), 256, SM_PROJ>>>(x, Wq, Wk, Wv);
    k_bnstats<<<128, 256>>>(gamma_q, beta_q, gamma_v, beta_v);
    k_lamc<<<BATCH * 16, 256>>>();
    k_final<<<dim3(8, 8, BATCH), 512, smemK5>>>(R, out);
}

// round 11
// speedup vs baseline: 1.5743x; 1.0395x over previous
#include <cuda_runtime.h>
#include <cuda_bf16.h>
#include <math.h>

// ---------------- problem constants ----------------
#define BATCH   16
#define CIN     256
#define IMGH    64
#define IMGW    64
#define NPIX    4096
#define HEADS   4
#define DK      16
#define DV      64
#define RKS     7
#define TAPS    49
#define PADR    3

#define N_OUT   144        // 64 q + 16 k + 64 v
#define MT      128        // pixels per CTA tile
#define KCH     64         // K-chunk staged per iteration

// smem byte offsets for k_proj (A: [k][pix] bf16, B: [out][k] bf16)
#define PITCH_A 272
#define PITCH_B 144
#define OFF_AHI 0
#define OFF_ALO (OFF_AHI + KCH * PITCH_A)
#define OFF_BHI (OFF_ALO + KCH * PITCH_A)
#define OFF_BLO (OFF_BHI + N_OUT * PITCH_B)
#define SM_PROJ (OFF_BLO + N_OUT * PITCH_B)
#define DPITCH  132

// ---------------- device scratch ----------------
__device__ float g_q[BATCH * 64 * NPIX];
__device__ float g_k[BATCH * 16 * NPIX];
__device__ float g_v[BATCH * 64 * NPIX];
__device__ float g_sq[64], g_bq[64];
__device__ float g_sv[64], g_bv[64];
__device__ float g_lamc[BATCH * 16 * 64];
// BN-stat partials from k_proj epilogue
__device__ float g_psum[128][512];          // [stat ch][b*32+tile]
__device__ float g_psq [128][512];
__device__ float g_pkmax[BATCH][16][32];    // [b][k][tile]
__device__ float g_kmax [BATCH][16];

// ---------------- helpers ----------------
__device__ __forceinline__ unsigned smem_u32(const void* p) {
    unsigned a;
    asm("{ .reg .u64 t; cvta.to.shared.u64 t, %1; cvt.u32.u64 %0, t; }" : "=r"(a) : "l"(p));
    return a;
}
__device__ __forceinline__ void ldsm_x4t(unsigned addr, unsigned& r0, unsigned& r1,
                                         unsigned& r2, unsigned& r3) {
    asm volatile("ldmatrix.sync.aligned.m8n8.x4.trans.shared.b16 {%0,%1,%2,%3}, [%4];"
                 : "=r"(r0), "=r"(r1), "=r"(r2), "=r"(r3) : "r"(addr));
}
__device__ __forceinline__ void ldsm_x2(unsigned addr, unsigned& r0, unsigned& r1) {
    asm volatile("ldmatrix.sync.aligned.m8n8.x2.shared.b16 {%0,%1}, [%2];"
                 : "=r"(r0), "=r"(r1) : "r"(addr));
}
__device__ __forceinline__ void mma16816(float* d, const unsigned* a, unsigned b0, unsigned b1) {
    asm volatile(
        "mma.sync.aligned.m16n8k16.row.col.f32.bf16.bf16.f32 "
        "{%0,%1,%2,%3}, {%4,%5,%6,%7}, {%8,%9}, {%0,%1,%2,%3};"
        : "+f"(d[0]), "+f"(d[1]), "+f"(d[2]), "+f"(d[3])
        : "r"(a[0]), "r"(a[1]), "r"(a[2]), "r"(a[3]), "r"(b0), "r"(b1));
}
__device__ __forceinline__ void bf_split(float f, unsigned short& hi, unsigned short& lo) {
    __nv_bfloat16 h = __float2bfloat16_rn(f);
    __nv_bfloat16 l = __float2bfloat16_rn(f - __bfloat162float(h));
    hi = __bfloat16_as_ushort(h);
    lo = __bfloat16_as_ushort(l);
}

// ======================================================================
// K1: projection via mma.sync bf16 2-way split + BN-stat partials.
// ======================================================================
__global__ __launch_bounds__(256)
void k_proj(const float* __restrict__ x,
            const float* __restrict__ Wq,
            const float* __restrict__ Wk,
            const float* __restrict__ Wv) {
    extern __shared__ __align__(16) char smem[];
    const unsigned sb = smem_u32(smem);
    const int tid  = threadIdx.x;
    const int lane = tid & 31;
    const int wid  = tid >> 5;
    const int wm   = wid & 3;
    const int wn   = wid >> 2;
    const int b    = blockIdx.y;
    const int pix0 = blockIdx.x * MT;

    const float* xb = x + (size_t)b * CIN * NPIX + pix0;

    float acc[2][9][4];
#pragma unroll
    for (int mi = 0; mi < 2; ++mi)
#pragma unroll
        for (int ni = 0; ni < 9; ++ni)
#pragma unroll
            for (int r = 0; r < 4; ++r) acc[mi][ni][r] = 0.f;

    const int a_kl = (lane & 7) + ((lane >> 4) << 3);
    const int a_pl = ((lane >> 3) & 1) * 8;
    const int l15  = lane & 15;
    const int b_nl = l15 & 7;
    const int b_kl = ((l15 >> 3) & 1) * 8;

    for (int chunk = 0; chunk < 4; ++chunk) {
        const int c0 = chunk * KCH;

#pragma unroll
        for (int i = 0; i < 16; ++i) {
            int idx = tid + i * 256;
            int cc = idx >> 6, pq = idx & 63;
            float2 xv = *(const float2*)(xb + (size_t)(c0 + cc) * NPIX + pq * 2);
            unsigned short h0, l0, h1, l1;
            bf_split(xv.x, h0, l0);
            bf_split(xv.y, h1, l1);
            *(unsigned*)(smem + OFF_AHI + cc * PITCH_A + pq * 4) = (unsigned)h0 | ((unsigned)h1 << 16);
            *(unsigned*)(smem + OFF_ALO + cc * PITCH_A + pq * 4) = (unsigned)l0 | ((unsigned)l1 << 16);
        }
#pragma unroll
        for (int i = 0; i < 18; ++i) {
            int idx = tid + i * 256;
            int o = idx >> 5, kq = idx & 31;
            const float* wrow = (o < 64) ? (Wq + o * CIN)
                              : (o < 80) ? (Wk + (o - 64) * CIN)
                                         : (Wv + (o - 80) * CIN);
            float2 wv = *(const float2*)(wrow + c0 + kq * 2);
            unsigned short h0, l0, h1, l1;
            bf_split(wv.x, h0, l0);
            bf_split(wv.y, h1, l1);
            *(unsigned*)(smem + OFF_BHI + o * PITCH_B + kq * 4) = (unsigned)h0 | ((unsigned)h1 << 16);
            *(unsigned*)(smem + OFF_BLO + o * PITCH_B + kq * 4) = (unsigned)l0 | ((unsigned)l1 << 16);
        }
        __syncthreads();

#pragma unroll
        for (int ks = 0; ks < 4; ++ks) {
            unsigned ahi[2][4], alo[2][4];
#pragma unroll
            for (int mi = 0; mi < 2; ++mi) {
                unsigned aoff = (unsigned)((ks * 16 + a_kl) * PITCH_A
                                           + (wm * 32 + mi * 16 + a_pl) * 2);
                ldsm_x4t(sb + OFF_AHI + aoff, ahi[mi][0], ahi[mi][1], ahi[mi][2], ahi[mi][3]);
                ldsm_x4t(sb + OFF_ALO + aoff, alo[mi][0], alo[mi][1], alo[mi][2], alo[mi][3]);
            }
#pragma unroll
            for (int ni = 0; ni < 9; ++ni) {
                unsigned boff = (unsigned)((wn * 72 + ni * 8 + b_nl) * PITCH_B
                                           + (ks * 16 + b_kl) * 2);
                unsigned bh0, bh1, bl0, bl1;
                ldsm_x2(sb + OFF_BHI + boff, bh0, bh1);
                ldsm_x2(sb + OFF_BLO + boff, bl0, bl1);
#pragma unroll
                for (int mi = 0; mi < 2; ++mi) {
                    mma16816(acc[mi][ni], ahi[mi], bh0, bh1);
                    mma16816(acc[mi][ni], ahi[mi], bl0, bl1);
                    mma16816(acc[mi][ni], alo[mi], bh0, bh1);
                }
            }
        }
        __syncthreads();
    }

    // ---- epilogue: fragments -> smem D[o][pix] ----
    float* dsm = (float*)smem;
#pragma unroll
    for (int mi = 0; mi < 2; ++mi)
#pragma unroll
        for (int ni = 0; ni < 9; ++ni) {
            int o = wn * 72 + ni * 8 + (lane & 3) * 2;
            int p = wm * 32 + mi * 16 + (lane >> 2);
            dsm[o * DPITCH + p]           = acc[mi][ni][0];
            dsm[(o + 1) * DPITCH + p]     = acc[mi][ni][1];
            dsm[o * DPITCH + p + 8]       = acc[mi][ni][2];
            dsm[(o + 1) * DPITCH + p + 8] = acc[mi][ni][3];
        }
    __syncthreads();

    float* qd = g_q + (size_t)b * 64 * NPIX;
    float* kd = g_k + (size_t)b * 16 * NPIX;
    float* vd = g_v + (size_t)b * 64 * NPIX;
#pragma unroll
    for (int i = 0; i < 18; ++i) {
        int idx = tid + i * 256;
        int o = idx >> 5, p4 = idx & 31;
        float4 val = *(const float4*)(dsm + o * DPITCH + p4 * 4);
        float* dst;
        if (o < 64)      dst = qd + (size_t)o * NPIX;
        else if (o < 80) dst = kd + (size_t)(o - 64) * NPIX;
        else             dst = vd + (size_t)(o - 80) * NPIX;
        *(float4*)(dst + pix0 + p4 * 4) = val;
    }

    // ---- BN-stat partials from the smem tile ----
    if (tid < N_OUT) {
        const int o = tid;
        const float* row = dsm + o * DPITCH;
        if (o >= 64 && o < 80) {
            float m = -1e30f;
#pragma unroll
            for (int j = 0; j < 128; j += 4) {
                float4 v = *(const float4*)(row + j);
                m = fmaxf(m, fmaxf(fmaxf(v.x, v.y), fmaxf(v.z, v.w)));
            }
            g_pkmax[b][o - 64][blockIdx.x] = m;
        } else {
            float s = 0.f, s2 = 0.f;
#pragma unroll
            for (int j = 0; j < 128; j += 4) {
                float4 v = *(const float4*)(row + j);
                s  += v.x + v.y + v.z + v.w;
                s2 += v.x * v.x + v.y * v.y + v.z * v.z + v.w * v.w;
            }
            int ch = (o < 64) ? o : (o - 16);
            int slot = b * 32 + blockIdx.x;
            g_psum[ch][slot] = s;
            g_psq [ch][slot] = s2;
        }
    }
}

// ======================================================================
// K2: reduce stat partials -> BN fold params + k row maxes.
// grid = 192 blocks x 128 threads:
//   blocks 0..127   : channel ch sums -> g_s*/g_b*
//   blocks 128..191 : 4 warps, each one (b,k) max over 32 tiles
// ======================================================================
__global__ __launch_bounds__(128)
void k_reduce(const float* __restrict__ gamma_q, const float* __restrict__ beta_q,
              const float* __restrict__ gamma_v, const float* __restrict__ beta_v) {
    const int bid = blockIdx.x;
    const int tid = threadIdx.x;

    if (bid < 128) {
        const int ch = bid;
        float s = 0.f, s2 = 0.f;
#pragma unroll
        for (int i = tid; i < 512; i += 128) { s += g_psum[ch][i]; s2 += g_psq[ch][i]; }
        __shared__ float ss[128], ss2[128];
        ss[tid] = s; ss2[tid] = s2;
        __syncthreads();
        for (int st = 64; st > 0; st >>= 1) {
            if (tid < st) { ss[tid] += ss[tid + st]; ss2[tid] += ss2[tid + st]; }
            __syncthreads();
        }
        if (tid == 0) {
            const float inv_n = 1.0f / 65536.0f;
            float mean = ss[0] * inv_n;
            float var  = ss2[0] * inv_n - mean * mean;
            float gamma, beta;
            float *sd, *bd;
            if (ch < 64) { gamma = gamma_q[ch]; beta = beta_q[ch]; sd = &g_sq[ch]; bd = &g_bq[ch]; }
            else { int c = ch - 64; gamma = gamma_v[c]; beta = beta_v[c]; sd = &g_sv[c]; bd = &g_bv[c]; }
            float sc = gamma * rsqrtf(var + 1e-5f);
            *sd = sc;
            *bd = beta - mean * sc;
        }
    } else {
        const int warp = tid >> 5, lane = tid & 31;
        const int pair = (bid - 128) * 4 + warp;    // 0..255
        const int b = pair >> 4, kc = pair & 15;
        float m = g_pkmax[b][kc][lane];             // 32 tiles = 32 lanes
#pragma unroll
        for (int o = 16; o > 0; o >>= 1) m = fmaxf(m, __shfl_down_sync(0xffffffffu, m, o));
        if (lane == 0) g_kmax[b][kc] = m;
    }
}

// ======================================================================
// K3: softmax + lambda_c (max pass removed; uses g_kmax).
// ======================================================================
__global__ __launch_bounds__(256)
void k_lamc() {
    const int bk  = blockIdx.x;
    const int b   = bk >> 4;
    const int kc  = bk & 15;
    const int tid = threadIdx.x;
    const int lane = tid & 31, wrp = tid >> 5;

    const float* krow = g_k + ((size_t)b * 16 + kc) * NPIX;
    const float* vb   = g_v + (size_t)b * 64 * NPIX;

    const float m = g_kmax[b][kc];

    float acc[64];
#pragma unroll
    for (int v = 0; v < 64; ++v) acc[v] = 0.f;
    float z = 0.f;

    for (int i = tid; i < NPIX; i += 256) {
        float w = expf(krow[i] - m);
        z += w;
#pragma unroll
        for (int v = 0; v < 64; ++v) acc[v] += w * vb[(size_t)v * NPIX + i];
    }

    __shared__ float red[256];
    red[tid] = z;
    __syncthreads();
    for (int st = 128; st > 0; st >>= 1) {
        if (tid < st) red[tid] += red[tid + st];
        __syncthreads();
    }
    z = red[0];
    __syncthreads();
    const float invz = 1.0f / z;

    __shared__ float part[64][8];
#pragma unroll
    for (int v = 0; v < 64; ++v) {
        float xv = acc[v];
#pragma unroll
        for (int o = 16; o > 0; o >>= 1) xv += __shfl_down_sync(0xffffffffu, xv, o);
        if (lane == 0) part[v][wrp] = xv;
    }
    __syncthreads();
    if (tid < 64) {
        float sum = 0.f;
#pragma unroll
        for (int i = 0; i < 8; ++i) sum += part[tid][i];
        g_lamc[((size_t)b * 16 + kc) * 64 + tid] = g_sv[tid] * sum * invz + g_bv[tid];
    }
}

// ======================================================================
// K5: final fused output (R6 version — unchanged).
// ======================================================================
#define VHPITCH 68
#define QP      68
#define SP      28

__global__ __launch_bounds__(512, 2)
void k_final(const float* __restrict__ R, float* __restrict__ out) {
    extern __shared__ float sm[];
    float* q_sm    = sm;
    float* vh_sm   = q_sm + 64 * QP;
    float* s_sm    = vh_sm + 196 * VHPITCH;
    float* lamc_sm = s_sm + 64 * SP;
    float* R_sm    = lamc_sm + 1024;

    const int b   = blockIdx.z;
    const int tx0 = blockIdx.x * 8;
    const int ty0 = blockIdx.y * 8;
    const int tid = threadIdx.x;

    for (int i = tid; i < 784; i += 512)  R_sm[i]    = R[i];
    for (int i = tid; i < 1024; i += 512) lamc_sm[i] = g_lamc[(size_t)b * 1024 + i];

    {
        const float* qb = g_q + (size_t)b * 64 * NPIX;
        for (int idx = tid; idx < 4096; idx += 512) {
            int ch = idx >> 6, lp = idx & 63;
            int ly = lp >> 3,  lx = lp & 7;
            float v = qb[(size_t)ch * NPIX + (ty0 + ly) * IMGW + tx0 + lx];
            q_sm[lp * QP + ch] = v * g_sq[ch] + g_bq[ch];
        }
    }
    {
        const float* vb = g_v + (size_t)b * 64 * NPIX;
        for (int idx = tid; idx < 196 * 64; idx += 512) {
            int ch = idx / 196, hp = idx - ch * 196;
            int hy = hp / 14,   hx = hp - hy * 14;
            int gy = ty0 + hy - PADR, gx = tx0 + hx - PADR;
            float v = 0.f;
            if (gy >= 0 && gy < IMGH && gx >= 0 && gx < IMGW)
                v = vb[(size_t)ch * NPIX + gy * IMGW + gx] * g_sv[ch] + g_bv[ch];
            vh_sm[hp * VHPITCH + ch] = v;
        }
    }
    __syncthreads();

    const int g   = tid >> 6;
    const int pix = tid & 63;
    const int py  = pix >> 3, px = pix & 7;
    const float* qrow = q_sm + pix * QP;
    float* srow = s_sm + pix * SP;

    float acc[4][8];
#pragma unroll
    for (int h = 0; h < 4; ++h)
#pragma unroll
        for (int vi = 0; vi < 8; ++vi) acc[h][vi] = 0.f;

#pragma unroll
    for (int kk0 = 0; kk0 < 16; kk0 += 4) {
        float4 qh[4];
#pragma unroll
        for (int h = 0; h < 4; ++h)
            qh[h] = *(const float4*)(qrow + h * 16 + kk0);
#pragma unroll
        for (int j = 0; j < 4; ++j) {
            const float* lrow = lamc_sm + (kk0 + j) * 64 + g * 8;
            float4 l0 = ((const float4*)lrow)[0];
            float4 l1 = ((const float4*)lrow)[1];
            float lv[8] = {l0.x, l0.y, l0.z, l0.w, l1.x, l1.y, l1.z, l1.w};
            float q0 = (j == 0) ? qh[0].x : (j == 1) ? qh[0].y : (j == 2) ? qh[0].z : qh[0].w;
            float q1 = (j == 0) ? qh[1].x : (j == 1) ? qh[1].y : (j == 2) ? qh[1].z : qh[1].w;
            float q2 = (j == 0) ? qh[2].x : (j == 1) ? qh[2].y : (j == 2) ? qh[2].z : qh[2].w;
            float q3 = (j == 0) ? qh[3].x : (j == 1) ? qh[3].y : (j == 2) ? qh[3].z : qh[3].w;
#pragma unroll
            for (int vi = 0; vi < 8; ++vi) {
                acc[0][vi] += q0 * lv[vi];
                acc[1][vi] += q1 * lv[vi];
                acc[2][vi] += q2 * lv[vi];
                acc[3][vi] += q3 * lv[vi];
            }
        }
    }

    const int hs   = g & 3;
    const int ttlo = (g >> 2) ? 4 : 0;
    const int tthi = (g >> 2) ? 7 : 4;

    for (int dy = 0; dy < RKS; ++dy) {
        __syncthreads();
        {
            float4 qa  = *(const float4*)(qrow + hs * 16 + 0);
            float4 qb4 = *(const float4*)(qrow + hs * 16 + 4);
            float4 qc  = *(const float4*)(qrow + hs * 16 + 8);
            float4 qd  = *(const float4*)(qrow + hs * 16 + 12);
            float qk[16] = {qa.x, qa.y, qa.z, qa.w, qb4.x, qb4.y, qb4.z, qb4.w,
                            qc.x, qc.y, qc.z, qc.w, qd.x, qd.y, qd.z, qd.w};
            for (int tt = ttlo; tt < tthi; ++tt) {
                float s = 0.f;
#pragma unroll
                for (int kk = 0; kk < 16; ++kk) s += qk[kk] * R_sm[kk * TAPS + dy * RKS + tt];
                srow[tt * 4 + hs] = s;
            }
        }
        __syncthreads();

#pragma unroll
        for (int dx = 0; dx < RKS; ++dx) {
            const int hp = (py + dy) * 14 + (px + dx);
            const float4* vp = (const float4*)(vh_sm + hp * VHPITCH + g * 8);
            float4 v0 = vp[0], v1 = vp[1];
            float vv[8] = {v0.x, v0.y, v0.z, v0.w, v1.x, v1.y, v1.z, v1.w};
            float4 s4 = *(const float4*)(srow + dx * 4);
#pragma unroll
            for (int vi = 0; vi < 8; ++vi) {
                acc[0][vi] += s4.x * vv[vi];
                acc[1][vi] += s4.y * vv[vi];
                acc[2][vi] += s4.z * vv[vi];
                acc[3][vi] += s4.w * vv[vi];
            }
        }
    }

    const size_t ob = (size_t)b * 256 * NPIX;
    const int gp = (ty0 + py) * IMGW + tx0 + px;
#pragma unroll
    for (int h = 0; h < 4; ++h)
#pragma unroll
        for (int vi = 0; vi < 8; ++vi)
            out[ob + (size_t)(h * 64 + g * 8 + vi) * NPIX + gp] = acc[h][vi];
}

// ======================================================================
extern "C" void kernel_launch(void* const* d_in, const int* in_sizes, int n_in,
                              void* d_out, int out_size) {
    const float* x       = (const float*)d_in[0];
    const float* Wq      = (const float*)d_in[1];
    const float* Wk      = (const float*)d_in[2];
    const float* Wv      = (const float*)d_in[3];
    const float* gamma_q = (const float*)d_in[4];
    const float* beta_q  = (const float*)d_in[5];
    const float* gamma_v = (const float*)d_in[6];
    const float* beta_v  = (const float*)d_in[7];
    const float* R       = (const float*)d_in[8];
    float* out = (float*)d_out;

    cudaFuncSetAttribute(k_proj, cudaFuncAttributeMaxDynamicSharedMemorySize, SM_PROJ);
    const int smemK5 = (64 * QP + 196 * VHPITCH + 64 * SP + 1024 + 784) * (int)sizeof(float);
    cudaFuncSetAttribute(k_final, cudaFuncAttributeMaxDynamicSharedMemorySize, smemK5);

    k_proj<<<dim3(NPIX / MT, BATCH), 256, SM_PROJ>>>(x, Wq, Wk, Wv);
    k_reduce<<<192, 128>>>(gamma_q, beta_q, gamma_v, beta_v);
    k_lamc<<<BATCH * 16, 256>>>();
    k_final<<<dim3(8, 8, BATCH), 512, smemK5>>>(R, out);
}